// round 1
// baseline (speedup 1.0000x reference)
#include <cuda_runtime.h>
#include <math.h>

#define BATCH 2
#define SEQ 2048
#define DMODEL 1024
#define NTOK (BATCH*SEQ)
#define NH 16
#define DHD 64

// ---------------- scratch (static device allocations; no cudaMalloc) -------
__device__ float g_h[(size_t)NTOK * DMODEL];          // ln1 out
__device__ float g_qkv[(size_t)NTOK * 3 * DMODEL];    // qkv
__device__ float g_o[(size_t)NTOK * DMODEL];          // attn out
__device__ float g_h2[(size_t)NTOK * DMODEL];         // ln2 out
__device__ float g_up[(size_t)NTOK * 4 * DMODEL];     // mlp hidden

// ---------------- LayerNorm: one block per row, 256 threads ----------------
__global__ void __launch_bounds__(256) ln_kernel(const float* __restrict__ x,
                                                 const float* __restrict__ g,
                                                 const float* __restrict__ b,
                                                 float* __restrict__ out)
{
    const int row = blockIdx.x;
    const int t = threadIdx.x;
    const float4* xr = (const float4*)(x + (size_t)row * DMODEL);
    float4 v = xr[t];
    float s = v.x + v.y + v.z + v.w;
    float ss = v.x*v.x + v.y*v.y + v.z*v.z + v.w*v.w;

    #pragma unroll
    for (int off = 16; off > 0; off >>= 1) {
        s  += __shfl_xor_sync(0xffffffffu, s, off);
        ss += __shfl_xor_sync(0xffffffffu, ss, off);
    }
    __shared__ float s1[8], s2[8];
    const int warp = t >> 5, lane = t & 31;
    if (lane == 0) { s1[warp] = s; s2[warp] = ss; }
    __syncthreads();
    if (t == 0) {
        float a = 0.f, c = 0.f;
        #pragma unroll
        for (int i = 0; i < 8; i++) { a += s1[i]; c += s2[i]; }
        s1[0] = a; s2[0] = c;
    }
    __syncthreads();
    const float mean = s1[0] * (1.0f / DMODEL);
    const float var  = s2[0] * (1.0f / DMODEL) - mean * mean;
    const float rs = rsqrtf(var + 1e-5f);

    float4 gv = ((const float4*)g)[t];
    float4 bv = ((const float4*)b)[t];
    float4 o4;
    o4.x = (v.x - mean) * rs * gv.x + bv.x;
    o4.y = (v.y - mean) * rs * gv.y + bv.y;
    o4.z = (v.z - mean) * rs * gv.z + bv.z;
    o4.w = (v.w - mean) * rs * gv.w + bv.w;
    ((float4*)(out + (size_t)row * DMODEL))[t] = o4;
}

// ---------------- GELU ------------------------------------------------------
__device__ __forceinline__ float gelu_f(float x)
{
    const float c = 0.7978845608028654f;
    float inner = c * (x + 0.044715f * x * x * x);
    return 0.5f * x * (1.0f + tanhf(inner));
}

// ---------------- SGEMM NT: C[M,N] = A[M,K] @ B[N,K]^T + bias (+epi) -------
// EPI: 0 = none, 1 = +residual, 2 = gelu
template<int EPI>
__global__ void __launch_bounds__(256) sgemm_nt(const float* __restrict__ A,
                                                const float* __restrict__ B,
                                                const float* __restrict__ bias,
                                                const float* __restrict__ R,
                                                float* __restrict__ C,
                                                int M, int N, int K)
{
    __shared__ float As[8][128];
    __shared__ float Bs[8][128];

    const int tid = threadIdx.x;
    const int bm = blockIdx.y * 128;
    const int bn = blockIdx.x * 128;
    const int tx = tid & 15;
    const int ty = tid >> 4;
    const int lr = tid >> 1;          // 0..127
    const int lc = (tid & 1) << 2;    // 0 or 4

    const float* Ap = A + (size_t)(bm + lr) * K + lc;
    const float* Bp = B + (size_t)(bn + lr) * K + lc;

    float acc[8][8];
    #pragma unroll
    for (int i = 0; i < 8; i++)
        #pragma unroll
        for (int j = 0; j < 8; j++) acc[i][j] = 0.f;

    for (int k0 = 0; k0 < K; k0 += 8) {
        float4 a4 = *(const float4*)(Ap + k0);
        float4 b4 = *(const float4*)(Bp + k0);
        __syncthreads();
        As[lc + 0][lr] = a4.x; As[lc + 1][lr] = a4.y;
        As[lc + 2][lr] = a4.z; As[lc + 3][lr] = a4.w;
        Bs[lc + 0][lr] = b4.x; Bs[lc + 1][lr] = b4.y;
        Bs[lc + 2][lr] = b4.z; Bs[lc + 3][lr] = b4.w;
        __syncthreads();

        #pragma unroll
        for (int kk = 0; kk < 8; kk++) {
            float4 ra0 = *(const float4*)&As[kk][ty * 8];
            float4 ra1 = *(const float4*)&As[kk][ty * 8 + 4];
            float4 rb0 = *(const float4*)&Bs[kk][tx * 8];
            float4 rb1 = *(const float4*)&Bs[kk][tx * 8 + 4];
            float ra[8] = {ra0.x, ra0.y, ra0.z, ra0.w, ra1.x, ra1.y, ra1.z, ra1.w};
            float rb[8] = {rb0.x, rb0.y, rb0.z, rb0.w, rb1.x, rb1.y, rb1.z, rb1.w};
            #pragma unroll
            for (int i = 0; i < 8; i++)
                #pragma unroll
                for (int j = 0; j < 8; j++)
                    acc[i][j] = fmaf(ra[i], rb[j], acc[i][j]);
        }
    }

    // epilogue
    const int colb = bn + tx * 8;
    float4 bias0 = *(const float4*)(bias + colb);
    float4 bias1 = *(const float4*)(bias + colb + 4);
    float bb[8] = {bias0.x, bias0.y, bias0.z, bias0.w, bias1.x, bias1.y, bias1.z, bias1.w};

    #pragma unroll
    for (int i = 0; i < 8; i++) {
        const int row = bm + ty * 8 + i;
        float v[8];
        #pragma unroll
        for (int j = 0; j < 8; j++) {
            float t = acc[i][j] + bb[j];
            if (EPI == 2) t = gelu_f(t);
            v[j] = t;
        }
        if (EPI == 1) {
            const float* rrow = R + (size_t)row * N + colb;
            float4 r0 = *(const float4*)(rrow);
            float4 r1 = *(const float4*)(rrow + 4);
            v[0] += r0.x; v[1] += r0.y; v[2] += r0.z; v[3] += r0.w;
            v[4] += r1.x; v[5] += r1.y; v[6] += r1.z; v[7] += r1.w;
        }
        float* crow = C + (size_t)row * N + colb;
        *(float4*)(crow)     = make_float4(v[0], v[1], v[2], v[3]);
        *(float4*)(crow + 4) = make_float4(v[4], v[5], v[6], v[7]);
    }
}

// ---------------- Flash attention (causal), fp32 ---------------------------
// grid: (SEQ/64, NH, BATCH), block 256.
// smem: Qt[64][68] (d-major), KP[64][68] (Kt then P reuse), Vs[64][64]
#define QS 68

__global__ void __launch_bounds__(256) attn_kernel(const float* __restrict__ qkv,
                                                   float* __restrict__ o)
{
    extern __shared__ float sm[];
    float* Qt = sm;                 // [d][r], stride QS
    float* KP = sm + 64 * QS;       // Kt: [d][j]; later P: [j][r]
    float* Vs = sm + 2 * 64 * QS;   // [j][c], stride 64

    const int tid = threadIdx.x;
    const int qt = blockIdx.x;
    const int head = blockIdx.y;
    const int bb = blockIdx.z;

    const int tc = tid & 15;
    const int tr = tid >> 4;
    const int r0 = tr * 4;
    const int c0 = tc * 4;

    const size_t base = (size_t)bb * SEQ * (3 * DMODEL);
    const int hoff = head * DHD;

    // load Q tile, transposed into Qt[d][r]
    {
        const int r = tid >> 2;
        const int d0 = (tid & 3) << 4;
        const float* src = qkv + base + (size_t)(qt * 64 + r) * (3 * DMODEL) + hoff + d0;
        #pragma unroll
        for (int i = 0; i < 16; i += 4) {
            float4 v = *(const float4*)(src + i);
            Qt[(d0 + i + 0) * QS + r] = v.x;
            Qt[(d0 + i + 1) * QS + r] = v.y;
            Qt[(d0 + i + 2) * QS + r] = v.z;
            Qt[(d0 + i + 3) * QS + r] = v.w;
        }
    }

    float m[4], l[4], acc[4][4];
    #pragma unroll
    for (int i = 0; i < 4; i++) {
        m[i] = -1e30f; l[i] = 0.f;
        #pragma unroll
        for (int j = 0; j < 4; j++) acc[i][j] = 0.f;
    }

    for (int kt = 0; kt <= qt; kt++) {
        // prefetch K/V tile into registers
        const int r = tid >> 2;
        const int d0 = (tid & 3) << 4;
        const float* ksrc = qkv + base + (size_t)(kt * 64 + r) * (3 * DMODEL) + DMODEL + hoff + d0;
        const float* vsrc = ksrc + DMODEL;
        float4 kreg[4], vreg[4];
        #pragma unroll
        for (int i = 0; i < 4; i++) {
            kreg[i] = *(const float4*)(ksrc + 4 * i);
            vreg[i] = *(const float4*)(vsrc + 4 * i);
        }
        __syncthreads();   // previous iteration's PV reads complete
        #pragma unroll
        for (int i = 0; i < 4; i++) {
            const int d = d0 + 4 * i;
            KP[(d + 0) * QS + r] = kreg[i].x;
            KP[(d + 1) * QS + r] = kreg[i].y;
            KP[(d + 2) * QS + r] = kreg[i].z;
            KP[(d + 3) * QS + r] = kreg[i].w;
            *(float4*)&Vs[r * 64 + d] = vreg[i];
        }
        __syncthreads();

        // scores: s[i][j] = sum_d Q[r0+i][d] * K[c0+j][d]
        float s[4][4];
        #pragma unroll
        for (int i = 0; i < 4; i++)
            #pragma unroll
            for (int j = 0; j < 4; j++) s[i][j] = 0.f;

        #pragma unroll 8
        for (int d = 0; d < 64; d++) {
            float4 q4 = *(const float4*)&Qt[d * QS + r0];
            float4 k4 = *(const float4*)&KP[d * QS + c0];
            float qa[4] = {q4.x, q4.y, q4.z, q4.w};
            float ka[4] = {k4.x, k4.y, k4.z, k4.w};
            #pragma unroll
            for (int i = 0; i < 4; i++)
                #pragma unroll
                for (int j = 0; j < 4; j++)
                    s[i][j] = fmaf(qa[i], ka[j], s[i][j]);
        }
        __syncthreads();   // everyone done reading KP (K tile)

        // scale + causal mask
        #pragma unroll
        for (int i = 0; i < 4; i++)
            #pragma unroll
            for (int j = 0; j < 4; j++) {
                float t = s[i][j] * 0.125f;
                if (kt == qt && (c0 + j) > (r0 + i)) t = -1e30f;
                s[i][j] = t;
            }

        // online softmax (row stats across the 16 lanes of this row group)
        #pragma unroll
        for (int i = 0; i < 4; i++) {
            float rm = fmaxf(fmaxf(s[i][0], s[i][1]), fmaxf(s[i][2], s[i][3]));
            #pragma unroll
            for (int off = 1; off < 16; off <<= 1)
                rm = fmaxf(rm, __shfl_xor_sync(0xffffffffu, rm, off));
            float mn = fmaxf(m[i], rm);
            float corr = __expf(m[i] - mn);
            m[i] = mn;
            float ps = 0.f;
            #pragma unroll
            for (int j = 0; j < 4; j++) {
                s[i][j] = __expf(s[i][j] - mn);
                ps += s[i][j];
            }
            #pragma unroll
            for (int off = 1; off < 16; off <<= 1)
                ps += __shfl_xor_sync(0xffffffffu, ps, off);
            l[i] = l[i] * corr + ps;
            #pragma unroll
            for (int j = 0; j < 4; j++) acc[i][j] *= corr;
        }

        // write P (transposed): P[j][r]
        #pragma unroll
        for (int j = 0; j < 4; j++) {
            float4 pv = make_float4(s[0][j], s[1][j], s[2][j], s[3][j]);
            *(float4*)&KP[(c0 + j) * QS + r0] = pv;
        }
        __syncthreads();

        // O += P @ V
        #pragma unroll 8
        for (int jj = 0; jj < 64; jj++) {
            float4 p4 = *(const float4*)&KP[jj * QS + r0];
            float4 v4 = *(const float4*)&Vs[jj * 64 + c0];
            float pa[4] = {p4.x, p4.y, p4.z, p4.w};
            float va[4] = {v4.x, v4.y, v4.z, v4.w};
            #pragma unroll
            for (int i = 0; i < 4; i++)
                #pragma unroll
                for (int c = 0; c < 4; c++)
                    acc[i][c] = fmaf(pa[i], va[c], acc[i][c]);
        }
    }

    // write O
    #pragma unroll
    for (int i = 0; i < 4; i++) {
        const float inv = 1.0f / l[i];
        float* dst = o + (size_t)(bb * SEQ + qt * 64 + r0 + i) * DMODEL + hoff + c0;
        *(float4*)dst = make_float4(acc[i][0] * inv, acc[i][1] * inv,
                                    acc[i][2] * inv, acc[i][3] * inv);
    }
}

// ---------------- launch ----------------------------------------------------
extern "C" void kernel_launch(void* const* d_in, const int* in_sizes, int n_in,
                              void* d_out, int out_size)
{
    const float* x      = (const float*)d_in[0];
    const float* ln1_g  = (const float*)d_in[1];
    const float* ln1_b  = (const float*)d_in[2];
    const float* W_attn = (const float*)d_in[3];
    const float* b_attn = (const float*)d_in[4];
    const float* W_proj = (const float*)d_in[5];
    const float* b_proj = (const float*)d_in[6];
    const float* ln2_g  = (const float*)d_in[7];
    const float* ln2_b  = (const float*)d_in[8];
    const float* W_up   = (const float*)d_in[9];
    const float* b_up   = (const float*)d_in[10];
    const float* W_down = (const float*)d_in[11];
    const float* b_down = (const float*)d_in[12];
    float* out = (float*)d_out;

    float *h, *qkv, *o, *h2, *up;
    cudaGetSymbolAddress((void**)&h,   g_h);
    cudaGetSymbolAddress((void**)&qkv, g_qkv);
    cudaGetSymbolAddress((void**)&o,   g_o);
    cudaGetSymbolAddress((void**)&h2,  g_h2);
    cudaGetSymbolAddress((void**)&up,  g_up);

    const int attn_smem = (2 * 64 * QS + 64 * 64) * sizeof(float);   // 51200 B
    cudaFuncSetAttribute(attn_kernel, cudaFuncAttributeMaxDynamicSharedMemorySize, attn_smem);

    // 1. LN1
    ln_kernel<<<NTOK, 256>>>(x, ln1_g, ln1_b, h);
    // 2. QKV = h @ W_attn^T + b_attn   [4096, 3072]
    sgemm_nt<0><<<dim3(3 * DMODEL / 128, NTOK / 128), 256>>>(h, W_attn, b_attn, nullptr, qkv,
                                                             NTOK, 3 * DMODEL, DMODEL);
    // 3. attention -> o
    attn_kernel<<<dim3(SEQ / 64, NH, BATCH), 256, attn_smem>>>(qkv, o);
    // 4. x2 = x + o @ W_proj^T + b_proj  -> out
    sgemm_nt<1><<<dim3(DMODEL / 128, NTOK / 128), 256>>>(o, W_proj, b_proj, x, out,
                                                         NTOK, DMODEL, DMODEL);
    // 5. LN2
    ln_kernel<<<NTOK, 256>>>(out, ln2_g, ln2_b, h2);
    // 6. up = gelu(h2 @ W_up^T + b_up)   [4096, 4096]
    sgemm_nt<2><<<dim3(4 * DMODEL / 128, NTOK / 128), 256>>>(h2, W_up, b_up, nullptr, up,
                                                             NTOK, 4 * DMODEL, DMODEL);
    // 7. out = x2 + up @ W_down^T + b_down
    sgemm_nt<1><<<dim3(DMODEL / 128, NTOK / 128), 256>>>(up, W_down, b_down, out, out,
                                                         NTOK, DMODEL, 4 * DMODEL);
}

// round 2
// speedup vs baseline: 1.4928x; 1.4928x over previous
#include <cuda_runtime.h>
#include <cuda_bf16.h>
#include <math.h>

#define BATCH 2
#define SEQ 2048
#define DMODEL 1024
#define NTOK (BATCH*SEQ)
#define NH 16
#define DHD 64
#define QS 68

// ---------------- scratch (static device arrays; no cudaMalloc) -------------
__device__ float g_qkv[(size_t)NTOK * 3 * DMODEL];               // qkv fp32
__device__ float g_o[(size_t)NTOK * DMODEL];                     // attn out fp32
__device__ __nv_bfloat16 g_Aa[(size_t)NTOK * 3 * DMODEL];        // A' (h / o / h2): 4096 x 3072
__device__ __nv_bfloat16 g_Aup[(size_t)NTOK * 3 * 4 * DMODEL];   // A' (up): 4096 x 12288
__device__ __nv_bfloat16 g_Bw[(size_t)(4 * DMODEL) * 3 * DMODEL];// B' max: 12.6M elems

// ---------------- GELU ------------------------------------------------------
__device__ __forceinline__ float gelu_f(float x)
{
    const float c = 0.7978845608028654f;
    float inner = c * (x + 0.044715f * x * x * x);
    return 0.5f * x * (1.0f + tanhf(inner));
}

// ---------------- LayerNorm fused with bf16 split-triple output -------------
// Writes Y[row][3*DMODEL] = [hi | lo | hi]
__global__ void __launch_bounds__(256) ln_bf16_kernel(const float* __restrict__ x,
                                                      const float* __restrict__ g,
                                                      const float* __restrict__ b,
                                                      __nv_bfloat16* __restrict__ Y)
{
    const int row = blockIdx.x;
    const int t = threadIdx.x;
    const float4* xr = (const float4*)(x + (size_t)row * DMODEL);
    float4 v = xr[t];
    float s = v.x + v.y + v.z + v.w;
    float ss = v.x*v.x + v.y*v.y + v.z*v.z + v.w*v.w;

    #pragma unroll
    for (int off = 16; off > 0; off >>= 1) {
        s  += __shfl_xor_sync(0xffffffffu, s, off);
        ss += __shfl_xor_sync(0xffffffffu, ss, off);
    }
    __shared__ float s1[8], s2[8];
    const int warp = t >> 5, lane = t & 31;
    if (lane == 0) { s1[warp] = s; s2[warp] = ss; }
    __syncthreads();
    if (t == 0) {
        float a = 0.f, c = 0.f;
        #pragma unroll
        for (int i = 0; i < 8; i++) { a += s1[i]; c += s2[i]; }
        s1[0] = a; s2[0] = c;
    }
    __syncthreads();
    const float mean = s1[0] * (1.0f / DMODEL);
    const float var  = s2[0] * (1.0f / DMODEL) - mean * mean;
    const float rs = rsqrtf(var + 1e-5f);

    float4 gv = ((const float4*)g)[t];
    float4 bv = ((const float4*)b)[t];
    float o0 = (v.x - mean) * rs * gv.x + bv.x;
    float o1 = (v.y - mean) * rs * gv.y + bv.y;
    float o2 = (v.z - mean) * rs * gv.z + bv.z;
    float o3 = (v.w - mean) * rs * gv.w + bv.w;

    __nv_bfloat16 h0 = __float2bfloat16(o0), h1 = __float2bfloat16(o1);
    __nv_bfloat16 h2 = __float2bfloat16(o2), h3 = __float2bfloat16(o3);
    __nv_bfloat16 l0 = __float2bfloat16(o0 - __bfloat162float(h0));
    __nv_bfloat16 l1 = __float2bfloat16(o1 - __bfloat162float(h1));
    __nv_bfloat16 l2 = __float2bfloat16(o2 - __bfloat162float(h2));
    __nv_bfloat16 l3 = __float2bfloat16(o3 - __bfloat162float(h3));

    const int col = t * 4;
    const size_t rb = (size_t)row * 3 * DMODEL;
    __nv_bfloat162 hh01; hh01.x = h0; hh01.y = h1;
    __nv_bfloat162 hh23; hh23.x = h2; hh23.y = h3;
    __nv_bfloat162 ll01; ll01.x = l0; ll01.y = l1;
    __nv_bfloat162 ll23; ll23.x = l2; ll23.y = l3;
    *(__nv_bfloat162*)&Y[rb + col]                  = hh01;
    *(__nv_bfloat162*)&Y[rb + col + 2]              = hh23;
    *(__nv_bfloat162*)&Y[rb + DMODEL + col]         = ll01;
    *(__nv_bfloat162*)&Y[rb + DMODEL + col + 2]     = ll23;
    *(__nv_bfloat162*)&Y[rb + 2*DMODEL + col]       = hh01;
    *(__nv_bfloat162*)&Y[rb + 2*DMODEL + col + 2]   = hh23;
}

// ---------------- converters -------------------------------------------------
// A-side: [hi | lo | hi]
__global__ void convA_kernel(const float* __restrict__ X, __nv_bfloat16* __restrict__ Y,
                             int R, int K)
{
    int idx = blockIdx.x * blockDim.x + threadIdx.x;
    if (idx >= R * K) return;
    int r = idx / K, k = idx - r * K;
    float w = X[idx];
    __nv_bfloat16 hi = __float2bfloat16(w);
    __nv_bfloat16 lo = __float2bfloat16(w - __bfloat162float(hi));
    size_t rb = (size_t)r * 3 * K;
    Y[rb + k] = hi; Y[rb + K + k] = lo; Y[rb + 2*K + k] = hi;
}
// B-side: [hi | hi | lo]
__global__ void convW_kernel(const float* __restrict__ W, __nv_bfloat16* __restrict__ Y,
                             int Nr, int K)
{
    int idx = blockIdx.x * blockDim.x + threadIdx.x;
    if (idx >= Nr * K) return;
    int n = idx / K, k = idx - n * K;
    float w = W[idx];
    __nv_bfloat16 hi = __float2bfloat16(w);
    __nv_bfloat16 lo = __float2bfloat16(w - __bfloat162float(hi));
    size_t rb = (size_t)n * 3 * K;
    Y[rb + k] = hi; Y[rb + K + k] = hi; Y[rb + 2*K + k] = lo;
}

// ---------------- bf16 tensor-core GEMM NT ----------------------------------
// C[M,N] = A'[M,Kp] @ B'[N,Kp]^T (+bias, +epi). Kp = 3*K (split-bf16 trick).
// Block 128x128, KT=32, 8 warps (4m x 2n), warp tile 32x64, mma m16n8k16.
// EPI: 0 none (fp32 C), 1 +residual (fp32 C), 2 gelu -> bf16 split-triple C (A'-layout)
#define KT 32
#define SST 40

__device__ __forceinline__ void ldm4(unsigned &r0, unsigned &r1, unsigned &r2, unsigned &r3,
                                     unsigned a)
{
    asm volatile("ldmatrix.sync.aligned.m8n8.x4.shared.b16 {%0,%1,%2,%3}, [%4];"
        : "=r"(r0), "=r"(r1), "=r"(r2), "=r"(r3) : "r"(a));
}
__device__ __forceinline__ void mma_bf16(float* c, const unsigned* a, const unsigned* b)
{
    asm volatile("mma.sync.aligned.m16n8k16.row.col.f32.bf16.bf16.f32 "
        "{%0,%1,%2,%3}, {%4,%5,%6,%7}, {%8,%9}, {%0,%1,%2,%3};"
        : "+f"(c[0]), "+f"(c[1]), "+f"(c[2]), "+f"(c[3])
        : "r"(a[0]), "r"(a[1]), "r"(a[2]), "r"(a[3]), "r"(b[0]), "r"(b[1]));
}

template<int EPI>
__global__ void __launch_bounds__(256) gemm_bf16(const __nv_bfloat16* __restrict__ A,
                                                 const __nv_bfloat16* __restrict__ B,
                                                 const float* __restrict__ bias,
                                                 const float* __restrict__ R,
                                                 void* __restrict__ Cout,
                                                 int M, int N, int Kp)
{
    __shared__ __nv_bfloat16 As[2][128][SST];
    __shared__ __nv_bfloat16 Bs[2][128][SST];

    const int tid = threadIdx.x;
    const int lane = tid & 31, warp = tid >> 5;
    const int wm = warp >> 1, wn = warp & 1;
    const int bm = blockIdx.y * 128, bn = blockIdx.x * 128;

    const int lrow = tid >> 1;          // 0..127
    const int lck  = (tid & 1) * 16;    // bf16 element offset within k-tile
    const __nv_bfloat16* Ag = A + (size_t)(bm + lrow) * Kp + lck;
    const __nv_bfloat16* Bg = B + (size_t)(bn + lrow) * Kp + lck;

    float acc[2][8][4];
    #pragma unroll
    for (int i = 0; i < 2; i++)
        #pragma unroll
        for (int j = 0; j < 8; j++)
            #pragma unroll
            for (int q = 0; q < 4; q++) acc[i][j][q] = 0.f;

    const int nk = Kp / KT;

    // prologue: tile 0
    {
        unsigned sa = (unsigned)__cvta_generic_to_shared(&As[0][lrow][lck]);
        unsigned sb = (unsigned)__cvta_generic_to_shared(&Bs[0][lrow][lck]);
        asm volatile(
            "cp.async.cg.shared.global [%0], [%1], 16;\n"
            "cp.async.cg.shared.global [%2], [%3], 16;\n"
            "cp.async.cg.shared.global [%4], [%5], 16;\n"
            "cp.async.cg.shared.global [%6], [%7], 16;\n"
            :: "r"(sa), "l"(Ag), "r"(sa + 16), "l"(Ag + 8),
               "r"(sb), "l"(Bg), "r"(sb + 16), "l"(Bg + 8));
        asm volatile("cp.async.commit_group;");
    }

    for (int kt = 0; kt < nk; kt++) {
        if (kt + 1 < nk) {
            const int nb = (kt + 1) & 1;
            unsigned sa = (unsigned)__cvta_generic_to_shared(&As[nb][lrow][lck]);
            unsigned sb = (unsigned)__cvta_generic_to_shared(&Bs[nb][lrow][lck]);
            const __nv_bfloat16* ag = Ag + (kt + 1) * KT;
            const __nv_bfloat16* bg = Bg + (kt + 1) * KT;
            asm volatile(
                "cp.async.cg.shared.global [%0], [%1], 16;\n"
                "cp.async.cg.shared.global [%2], [%3], 16;\n"
                "cp.async.cg.shared.global [%4], [%5], 16;\n"
                "cp.async.cg.shared.global [%6], [%7], 16;\n"
                :: "r"(sa), "l"(ag), "r"(sa + 16), "l"(ag + 8),
                   "r"(sb), "l"(bg), "r"(sb + 16), "l"(bg + 8));
            asm volatile("cp.async.commit_group;");
            asm volatile("cp.async.wait_group 1;");
        } else {
            asm volatile("cp.async.wait_group 0;");
        }
        __syncthreads();

        const int cb = kt & 1;
        #pragma unroll
        for (int ks = 0; ks < 2; ks++) {
            unsigned af[2][4];
            unsigned bfr[8][2];
            #pragma unroll
            for (int mt = 0; mt < 2; mt++) {
                unsigned a = (unsigned)__cvta_generic_to_shared(
                    &As[cb][wm * 32 + mt * 16 + (lane & 15)][ks * 16 + (lane >> 4) * 8]);
                ldm4(af[mt][0], af[mt][1], af[mt][2], af[mt][3], a);
            }
            #pragma unroll
            for (int np = 0; np < 4; np++) {
                unsigned r0, r1, r2, r3;
                unsigned a = (unsigned)__cvta_generic_to_shared(
                    &Bs[cb][wn * 64 + np * 16 + (lane & 15)][ks * 16 + (lane >> 4) * 8]);
                ldm4(r0, r1, r2, r3, a);
                bfr[np*2][0]   = r0; bfr[np*2][1]   = r2;
                bfr[np*2+1][0] = r1; bfr[np*2+1][1] = r3;
            }
            #pragma unroll
            for (int mt = 0; mt < 2; mt++)
                #pragma unroll
                for (int nt = 0; nt < 8; nt++)
                    mma_bf16(acc[mt][nt], af[mt], bfr[nt]);
        }
        __syncthreads();
    }

    // epilogue
    const int rb0 = bm + wm * 32 + (lane >> 2);
    const int cb0 = bn + wn * 64 + (lane & 3) * 2;
    #pragma unroll
    for (int mt = 0; mt < 2; mt++) {
        #pragma unroll
        for (int nt = 0; nt < 8; nt++) {
            const int col = cb0 + nt * 8;
            float2 bs2 = *(const float2*)&bias[col];
            const int r0 = rb0 + mt * 16;
            const int r1 = r0 + 8;
            float v00 = acc[mt][nt][0] + bs2.x;
            float v01 = acc[mt][nt][1] + bs2.y;
            float v10 = acc[mt][nt][2] + bs2.x;
            float v11 = acc[mt][nt][3] + bs2.y;
            if (EPI == 2) {
                v00 = gelu_f(v00); v01 = gelu_f(v01);
                v10 = gelu_f(v10); v11 = gelu_f(v11);
                __nv_bfloat16* Y = (__nv_bfloat16*)Cout;
                __nv_bfloat16 h00 = __float2bfloat16(v00), h01 = __float2bfloat16(v01);
                __nv_bfloat16 h10 = __float2bfloat16(v10), h11 = __float2bfloat16(v11);
                __nv_bfloat16 l00 = __float2bfloat16(v00 - __bfloat162float(h00));
                __nv_bfloat16 l01 = __float2bfloat16(v01 - __bfloat162float(h01));
                __nv_bfloat16 l10 = __float2bfloat16(v10 - __bfloat162float(h10));
                __nv_bfloat16 l11 = __float2bfloat16(v11 - __bfloat162float(h11));
                __nv_bfloat162 hh0; hh0.x = h00; hh0.y = h01;
                __nv_bfloat162 hh1; hh1.x = h10; hh1.y = h11;
                __nv_bfloat162 ll0; ll0.x = l00; ll0.y = l01;
                __nv_bfloat162 ll1; ll1.x = l10; ll1.y = l11;
                const size_t b0 = (size_t)r0 * 3 * N + col;
                const size_t b1 = (size_t)r1 * 3 * N + col;
                *(__nv_bfloat162*)&Y[b0]         = hh0;
                *(__nv_bfloat162*)&Y[b0 + N]     = ll0;
                *(__nv_bfloat162*)&Y[b0 + 2*N]   = hh0;
                *(__nv_bfloat162*)&Y[b1]         = hh1;
                *(__nv_bfloat162*)&Y[b1 + N]     = ll1;
                *(__nv_bfloat162*)&Y[b1 + 2*N]   = hh1;
            } else {
                float* C = (float*)Cout;
                if (EPI == 1) {
                    float2 x0 = *(const float2*)&R[(size_t)r0 * N + col];
                    float2 x1 = *(const float2*)&R[(size_t)r1 * N + col];
                    v00 += x0.x; v01 += x0.y; v10 += x1.x; v11 += x1.y;
                }
                float2 o0; o0.x = v00; o0.y = v01;
                float2 o1; o1.x = v10; o1.y = v11;
                *(float2*)&C[(size_t)r0 * N + col] = o0;
                *(float2*)&C[(size_t)r1 * N + col] = o1;
            }
        }
    }
}

// ---------------- Flash attention (causal), fp32 (unchanged from R1) --------
__global__ void __launch_bounds__(256) attn_kernel(const float* __restrict__ qkv,
                                                   float* __restrict__ o)
{
    extern __shared__ float sm[];
    float* Qt = sm;
    float* KP = sm + 64 * QS;
    float* Vs = sm + 2 * 64 * QS;

    const int tid = threadIdx.x;
    const int qt = blockIdx.x;
    const int head = blockIdx.y;
    const int bb = blockIdx.z;

    const int tc = tid & 15;
    const int tr = tid >> 4;
    const int r0 = tr * 4;
    const int c0 = tc * 4;

    const size_t base = (size_t)bb * SEQ * (3 * DMODEL);
    const int hoff = head * DHD;

    {
        const int r = tid >> 2;
        const int d0 = (tid & 3) << 4;
        const float* src = qkv + base + (size_t)(qt * 64 + r) * (3 * DMODEL) + hoff + d0;
        #pragma unroll
        for (int i = 0; i < 16; i += 4) {
            float4 v = *(const float4*)(src + i);
            Qt[(d0 + i + 0) * QS + r] = v.x;
            Qt[(d0 + i + 1) * QS + r] = v.y;
            Qt[(d0 + i + 2) * QS + r] = v.z;
            Qt[(d0 + i + 3) * QS + r] = v.w;
        }
    }

    float m[4], l[4], acc[4][4];
    #pragma unroll
    for (int i = 0; i < 4; i++) {
        m[i] = -1e30f; l[i] = 0.f;
        #pragma unroll
        for (int j = 0; j < 4; j++) acc[i][j] = 0.f;
    }

    for (int kt = 0; kt <= qt; kt++) {
        const int r = tid >> 2;
        const int d0 = (tid & 3) << 4;
        const float* ksrc = qkv + base + (size_t)(kt * 64 + r) * (3 * DMODEL) + DMODEL + hoff + d0;
        const float* vsrc = ksrc + DMODEL;
        float4 kreg[4], vreg[4];
        #pragma unroll
        for (int i = 0; i < 4; i++) {
            kreg[i] = *(const float4*)(ksrc + 4 * i);
            vreg[i] = *(const float4*)(vsrc + 4 * i);
        }
        __syncthreads();
        #pragma unroll
        for (int i = 0; i < 4; i++) {
            const int d = d0 + 4 * i;
            KP[(d + 0) * QS + r] = kreg[i].x;
            KP[(d + 1) * QS + r] = kreg[i].y;
            KP[(d + 2) * QS + r] = kreg[i].z;
            KP[(d + 3) * QS + r] = kreg[i].w;
            *(float4*)&Vs[r * 64 + d] = vreg[i];
        }
        __syncthreads();

        float s[4][4];
        #pragma unroll
        for (int i = 0; i < 4; i++)
            #pragma unroll
            for (int j = 0; j < 4; j++) s[i][j] = 0.f;

        #pragma unroll 8
        for (int d = 0; d < 64; d++) {
            float4 q4 = *(const float4*)&Qt[d * QS + r0];
            float4 k4 = *(const float4*)&KP[d * QS + c0];
            float qa[4] = {q4.x, q4.y, q4.z, q4.w};
            float ka[4] = {k4.x, k4.y, k4.z, k4.w};
            #pragma unroll
            for (int i = 0; i < 4; i++)
                #pragma unroll
                for (int j = 0; j < 4; j++)
                    s[i][j] = fmaf(qa[i], ka[j], s[i][j]);
        }
        __syncthreads();

        #pragma unroll
        for (int i = 0; i < 4; i++)
            #pragma unroll
            for (int j = 0; j < 4; j++) {
                float t = s[i][j] * 0.125f;
                if (kt == qt && (c0 + j) > (r0 + i)) t = -1e30f;
                s[i][j] = t;
            }

        #pragma unroll
        for (int i = 0; i < 4; i++) {
            float rm = fmaxf(fmaxf(s[i][0], s[i][1]), fmaxf(s[i][2], s[i][3]));
            #pragma unroll
            for (int off = 1; off < 16; off <<= 1)
                rm = fmaxf(rm, __shfl_xor_sync(0xffffffffu, rm, off));
            float mn = fmaxf(m[i], rm);
            float corr = __expf(m[i] - mn);
            m[i] = mn;
            float ps = 0.f;
            #pragma unroll
            for (int j = 0; j < 4; j++) {
                s[i][j] = __expf(s[i][j] - mn);
                ps += s[i][j];
            }
            #pragma unroll
            for (int off = 1; off < 16; off <<= 1)
                ps += __shfl_xor_sync(0xffffffffu, ps, off);
            l[i] = l[i] * corr + ps;
            #pragma unroll
            for (int j = 0; j < 4; j++) acc[i][j] *= corr;
        }

        #pragma unroll
        for (int j = 0; j < 4; j++) {
            float4 pv = make_float4(s[0][j], s[1][j], s[2][j], s[3][j]);
            *(float4*)&KP[(c0 + j) * QS + r0] = pv;
        }
        __syncthreads();

        #pragma unroll 8
        for (int jj = 0; jj < 64; jj++) {
            float4 p4 = *(const float4*)&KP[jj * QS + r0];
            float4 v4 = *(const float4*)&Vs[jj * 64 + c0];
            float pa[4] = {p4.x, p4.y, p4.z, p4.w};
            float va[4] = {v4.x, v4.y, v4.z, v4.w};
            #pragma unroll
            for (int i = 0; i < 4; i++)
                #pragma unroll
                for (int c = 0; c < 4; c++)
                    acc[i][c] = fmaf(pa[i], va[c], acc[i][c]);
        }
    }

    #pragma unroll
    for (int i = 0; i < 4; i++) {
        const float inv = 1.0f / l[i];
        float* dst = o + (size_t)(bb * SEQ + qt * 64 + r0 + i) * DMODEL + hoff + c0;
        *(float4*)dst = make_float4(acc[i][0] * inv, acc[i][1] * inv,
                                    acc[i][2] * inv, acc[i][3] * inv);
    }
}

// ---------------- launch ----------------------------------------------------
extern "C" void kernel_launch(void* const* d_in, const int* in_sizes, int n_in,
                              void* d_out, int out_size)
{
    const float* x      = (const float*)d_in[0];
    const float* ln1_g  = (const float*)d_in[1];
    const float* ln1_b  = (const float*)d_in[2];
    const float* W_attn = (const float*)d_in[3];
    const float* b_attn = (const float*)d_in[4];
    const float* W_proj = (const float*)d_in[5];
    const float* b_proj = (const float*)d_in[6];
    const float* ln2_g  = (const float*)d_in[7];
    const float* ln2_b  = (const float*)d_in[8];
    const float* W_up   = (const float*)d_in[9];
    const float* b_up   = (const float*)d_in[10];
    const float* W_down = (const float*)d_in[11];
    const float* b_down = (const float*)d_in[12];
    float* out = (float*)d_out;

    float *qkv, *o;
    __nv_bfloat16 *Aa, *Aup, *Bw;
    cudaGetSymbolAddress((void**)&qkv, g_qkv);
    cudaGetSymbolAddress((void**)&o,   g_o);
    cudaGetSymbolAddress((void**)&Aa,  g_Aa);
    cudaGetSymbolAddress((void**)&Aup, g_Aup);
    cudaGetSymbolAddress((void**)&Bw,  g_Bw);

    const int attn_smem = (2 * 64 * QS + 64 * 64) * sizeof(float);
    cudaFuncSetAttribute(attn_kernel, cudaFuncAttributeMaxDynamicSharedMemorySize, attn_smem);

    // 1. LN1 -> Aa (bf16 split triple)
    ln_bf16_kernel<<<NTOK, 256>>>(x, ln1_g, ln1_b, Aa);
    // 2. W_attn -> Bw
    convW_kernel<<<(3 * DMODEL * DMODEL + 255) / 256, 256>>>(W_attn, Bw, 3 * DMODEL, DMODEL);
    // 3. qkv = h @ W_attn^T + b_attn
    gemm_bf16<0><<<dim3(3 * DMODEL / 128, NTOK / 128), 256>>>(Aa, Bw, b_attn, nullptr, qkv,
                                                              NTOK, 3 * DMODEL, 3 * DMODEL);
    // 4. attention -> o (fp32)
    attn_kernel<<<dim3(SEQ / 64, NH, BATCH), 256, attn_smem>>>(qkv, o);
    // 5. o -> Aa
    convA_kernel<<<(NTOK * DMODEL + 255) / 256, 256>>>(o, Aa, NTOK, DMODEL);
    // 6. W_proj -> Bw
    convW_kernel<<<(DMODEL * DMODEL + 255) / 256, 256>>>(W_proj, Bw, DMODEL, DMODEL);
    // 7. out = x + o @ W_proj^T + b_proj
    gemm_bf16<1><<<dim3(DMODEL / 128, NTOK / 128), 256>>>(Aa, Bw, b_proj, x, out,
                                                          NTOK, DMODEL, 3 * DMODEL);
    // 8. LN2 -> Aa
    ln_bf16_kernel<<<NTOK, 256>>>(out, ln2_g, ln2_b, Aa);
    // 9. W_up -> Bw
    convW_kernel<<<(4 * DMODEL * DMODEL + 255) / 256, 256>>>(W_up, Bw, 4 * DMODEL, DMODEL);
    // 10. Aup = split(gelu(h2 @ W_up^T + b_up))  (bf16 triple, EPI=2)
    gemm_bf16<2><<<dim3(4 * DMODEL / 128, NTOK / 128), 256>>>(Aa, Bw, b_up, nullptr, Aup,
                                                              NTOK, 4 * DMODEL, 3 * DMODEL);
    // 11. W_down -> Bw
    convW_kernel<<<(DMODEL * 4 * DMODEL + 255) / 256, 256>>>(W_down, Bw, DMODEL, 4 * DMODEL);
    // 12. out = out + up @ W_down^T + b_down
    gemm_bf16<1><<<dim3(DMODEL / 128, NTOK / 128), 256>>>(Aup, Bw, b_down, out, out,
                                                          NTOK, DMODEL, 3 * 4 * DMODEL);
}

// round 3
// speedup vs baseline: 1.7883x; 1.1979x over previous
#include <cuda_runtime.h>
#include <cuda_bf16.h>
#include <math.h>

#define BATCH 2
#define SEQ 2048
#define DMODEL 1024
#define NTOK (BATCH*SEQ)
#define NH 16
#define DHD 64

// ---------------- scratch (static device arrays; no cudaMalloc) -------------
__device__ float g_qkv[(size_t)NTOK * 3 * DMODEL];               // qkv fp32
__device__ float g_o[(size_t)NTOK * DMODEL];                     // attn out fp32
__device__ __nv_bfloat16 g_Aa[(size_t)NTOK * 3 * DMODEL];        // A' (h / o / h2)
__device__ __nv_bfloat16 g_Aup[(size_t)NTOK * 3 * 4 * DMODEL];   // A' (up)
__device__ __nv_bfloat16 g_Bw[(size_t)(4 * DMODEL) * 3 * DMODEL];// B'

// ---------------- GELU ------------------------------------------------------
__device__ __forceinline__ float gelu_f(float x)
{
    const float c = 0.7978845608028654f;
    float inner = c * (x + 0.044715f * x * x * x);
    return 0.5f * x * (1.0f + tanhf(inner));
}

// ---------------- LayerNorm fused with bf16 split-triple output -------------
__global__ void __launch_bounds__(256) ln_bf16_kernel(const float* __restrict__ x,
                                                      const float* __restrict__ g,
                                                      const float* __restrict__ b,
                                                      __nv_bfloat16* __restrict__ Y)
{
    const int row = blockIdx.x;
    const int t = threadIdx.x;
    const float4* xr = (const float4*)(x + (size_t)row * DMODEL);
    float4 v = xr[t];
    float s = v.x + v.y + v.z + v.w;
    float ss = v.x*v.x + v.y*v.y + v.z*v.z + v.w*v.w;

    #pragma unroll
    for (int off = 16; off > 0; off >>= 1) {
        s  += __shfl_xor_sync(0xffffffffu, s, off);
        ss += __shfl_xor_sync(0xffffffffu, ss, off);
    }
    __shared__ float s1[8], s2[8];
    const int warp = t >> 5, lane = t & 31;
    if (lane == 0) { s1[warp] = s; s2[warp] = ss; }
    __syncthreads();
    if (t == 0) {
        float a = 0.f, c = 0.f;
        #pragma unroll
        for (int i = 0; i < 8; i++) { a += s1[i]; c += s2[i]; }
        s1[0] = a; s2[0] = c;
    }
    __syncthreads();
    const float mean = s1[0] * (1.0f / DMODEL);
    const float var  = s2[0] * (1.0f / DMODEL) - mean * mean;
    const float rs = rsqrtf(var + 1e-5f);

    float4 gv = ((const float4*)g)[t];
    float4 bv = ((const float4*)b)[t];
    float o0 = (v.x - mean) * rs * gv.x + bv.x;
    float o1 = (v.y - mean) * rs * gv.y + bv.y;
    float o2 = (v.z - mean) * rs * gv.z + bv.z;
    float o3 = (v.w - mean) * rs * gv.w + bv.w;

    __nv_bfloat16 h0 = __float2bfloat16(o0), h1 = __float2bfloat16(o1);
    __nv_bfloat16 h2 = __float2bfloat16(o2), h3 = __float2bfloat16(o3);
    __nv_bfloat16 l0 = __float2bfloat16(o0 - __bfloat162float(h0));
    __nv_bfloat16 l1 = __float2bfloat16(o1 - __bfloat162float(h1));
    __nv_bfloat16 l2 = __float2bfloat16(o2 - __bfloat162float(h2));
    __nv_bfloat16 l3 = __float2bfloat16(o3 - __bfloat162float(h3));

    const int col = t * 4;
    const size_t rb = (size_t)row * 3 * DMODEL;
    __nv_bfloat162 hh01; hh01.x = h0; hh01.y = h1;
    __nv_bfloat162 hh23; hh23.x = h2; hh23.y = h3;
    __nv_bfloat162 ll01; ll01.x = l0; ll01.y = l1;
    __nv_bfloat162 ll23; ll23.x = l2; ll23.y = l3;
    *(__nv_bfloat162*)&Y[rb + col]                  = hh01;
    *(__nv_bfloat162*)&Y[rb + col + 2]              = hh23;
    *(__nv_bfloat162*)&Y[rb + DMODEL + col]         = ll01;
    *(__nv_bfloat162*)&Y[rb + DMODEL + col + 2]     = ll23;
    *(__nv_bfloat162*)&Y[rb + 2*DMODEL + col]       = hh01;
    *(__nv_bfloat162*)&Y[rb + 2*DMODEL + col + 2]   = hh23;
}

// ---------------- converters -------------------------------------------------
__global__ void convA_kernel(const float* __restrict__ X, __nv_bfloat16* __restrict__ Y,
                             int R, int K)
{
    int idx = blockIdx.x * blockDim.x + threadIdx.x;
    if (idx >= R * K) return;
    int r = idx / K, k = idx - r * K;
    float w = X[idx];
    __nv_bfloat16 hi = __float2bfloat16(w);
    __nv_bfloat16 lo = __float2bfloat16(w - __bfloat162float(hi));
    size_t rb = (size_t)r * 3 * K;
    Y[rb + k] = hi; Y[rb + K + k] = lo; Y[rb + 2*K + k] = hi;
}
__global__ void convW_kernel(const float* __restrict__ W, __nv_bfloat16* __restrict__ Y,
                             int Nr, int K)
{
    int idx = blockIdx.x * blockDim.x + threadIdx.x;
    if (idx >= Nr * K) return;
    int n = idx / K, k = idx - n * K;
    float w = W[idx];
    __nv_bfloat16 hi = __float2bfloat16(w);
    __nv_bfloat16 lo = __float2bfloat16(w - __bfloat162float(hi));
    size_t rb = (size_t)n * 3 * K;
    Y[rb + k] = hi; Y[rb + K + k] = hi; Y[rb + 2*K + k] = lo;
}

// ---------------- mma helpers ------------------------------------------------
__device__ __forceinline__ void ldm4(unsigned &r0, unsigned &r1, unsigned &r2, unsigned &r3,
                                     unsigned a)
{
    asm volatile("ldmatrix.sync.aligned.m8n8.x4.shared.b16 {%0,%1,%2,%3}, [%4];"
        : "=r"(r0), "=r"(r1), "=r"(r2), "=r"(r3) : "r"(a));
}
__device__ __forceinline__ void mma_bf16(float* c, const unsigned* a, const unsigned* b)
{
    asm volatile("mma.sync.aligned.m16n8k16.row.col.f32.bf16.bf16.f32 "
        "{%0,%1,%2,%3}, {%4,%5,%6,%7}, {%8,%9}, {%0,%1,%2,%3};"
        : "+f"(c[0]), "+f"(c[1]), "+f"(c[2]), "+f"(c[3])
        : "r"(a[0]), "r"(a[1]), "r"(a[2]), "r"(a[3]), "r"(b[0]), "r"(b[1]));
}
__device__ __forceinline__ unsigned pack_hi2(float a, float b)
{
    __nv_bfloat162 t; t.x = __float2bfloat16(a); t.y = __float2bfloat16(b);
    return *(unsigned*)&t;
}
__device__ __forceinline__ unsigned pack_lo2(float a, float b)
{
    float la = a - __bfloat162float(__float2bfloat16(a));
    float lb = b - __bfloat162float(__float2bfloat16(b));
    __nv_bfloat162 t; t.x = __float2bfloat16(la); t.y = __float2bfloat16(lb);
    return *(unsigned*)&t;
}

// ---------------- bf16 tensor-core GEMM NT (unchanged from R2) ---------------
#define KT 32
#define SST 40

template<int EPI>
__global__ void __launch_bounds__(256) gemm_bf16(const __nv_bfloat16* __restrict__ A,
                                                 const __nv_bfloat16* __restrict__ B,
                                                 const float* __restrict__ bias,
                                                 const float* __restrict__ R,
                                                 void* __restrict__ Cout,
                                                 int M, int N, int Kp)
{
    __shared__ __nv_bfloat16 As[2][128][SST];
    __shared__ __nv_bfloat16 Bs[2][128][SST];

    const int tid = threadIdx.x;
    const int lane = tid & 31, warp = tid >> 5;
    const int wm = warp >> 1, wn = warp & 1;
    const int bm = blockIdx.y * 128, bn = blockIdx.x * 128;

    const int lrow = tid >> 1;
    const int lck  = (tid & 1) * 16;
    const __nv_bfloat16* Ag = A + (size_t)(bm + lrow) * Kp + lck;
    const __nv_bfloat16* Bg = B + (size_t)(bn + lrow) * Kp + lck;

    float acc[2][8][4];
    #pragma unroll
    for (int i = 0; i < 2; i++)
        #pragma unroll
        for (int j = 0; j < 8; j++)
            #pragma unroll
            for (int q = 0; q < 4; q++) acc[i][j][q] = 0.f;

    const int nk = Kp / KT;

    {
        unsigned sa = (unsigned)__cvta_generic_to_shared(&As[0][lrow][lck]);
        unsigned sb = (unsigned)__cvta_generic_to_shared(&Bs[0][lrow][lck]);
        asm volatile(
            "cp.async.cg.shared.global [%0], [%1], 16;\n"
            "cp.async.cg.shared.global [%2], [%3], 16;\n"
            "cp.async.cg.shared.global [%4], [%5], 16;\n"
            "cp.async.cg.shared.global [%6], [%7], 16;\n"
            :: "r"(sa), "l"(Ag), "r"(sa + 16), "l"(Ag + 8),
               "r"(sb), "l"(Bg), "r"(sb + 16), "l"(Bg + 8));
        asm volatile("cp.async.commit_group;");
    }

    for (int kt = 0; kt < nk; kt++) {
        if (kt + 1 < nk) {
            const int nb = (kt + 1) & 1;
            unsigned sa = (unsigned)__cvta_generic_to_shared(&As[nb][lrow][lck]);
            unsigned sb = (unsigned)__cvta_generic_to_shared(&Bs[nb][lrow][lck]);
            const __nv_bfloat16* ag = Ag + (kt + 1) * KT;
            const __nv_bfloat16* bg = Bg + (kt + 1) * KT;
            asm volatile(
                "cp.async.cg.shared.global [%0], [%1], 16;\n"
                "cp.async.cg.shared.global [%2], [%3], 16;\n"
                "cp.async.cg.shared.global [%4], [%5], 16;\n"
                "cp.async.cg.shared.global [%6], [%7], 16;\n"
                :: "r"(sa), "l"(ag), "r"(sa + 16), "l"(ag + 8),
                   "r"(sb), "l"(bg), "r"(sb + 16), "l"(bg + 8));
            asm volatile("cp.async.commit_group;");
            asm volatile("cp.async.wait_group 1;");
        } else {
            asm volatile("cp.async.wait_group 0;");
        }
        __syncthreads();

        const int cb = kt & 1;
        #pragma unroll
        for (int ks = 0; ks < 2; ks++) {
            unsigned af[2][4];
            unsigned bfr[8][2];
            #pragma unroll
            for (int mt = 0; mt < 2; mt++) {
                unsigned a = (unsigned)__cvta_generic_to_shared(
                    &As[cb][wm * 32 + mt * 16 + (lane & 15)][ks * 16 + (lane >> 4) * 8]);
                ldm4(af[mt][0], af[mt][1], af[mt][2], af[mt][3], a);
            }
            #pragma unroll
            for (int np = 0; np < 4; np++) {
                unsigned r0, r1, r2, r3;
                unsigned a = (unsigned)__cvta_generic_to_shared(
                    &Bs[cb][wn * 64 + np * 16 + (lane & 15)][ks * 16 + (lane >> 4) * 8]);
                ldm4(r0, r1, r2, r3, a);
                bfr[np*2][0]   = r0; bfr[np*2][1]   = r2;
                bfr[np*2+1][0] = r1; bfr[np*2+1][1] = r3;
            }
            #pragma unroll
            for (int mt = 0; mt < 2; mt++)
                #pragma unroll
                for (int nt = 0; nt < 8; nt++)
                    mma_bf16(acc[mt][nt], af[mt], bfr[nt]);
        }
        __syncthreads();
    }

    const int rb0 = bm + wm * 32 + (lane >> 2);
    const int cb0 = bn + wn * 64 + (lane & 3) * 2;
    #pragma unroll
    for (int mt = 0; mt < 2; mt++) {
        #pragma unroll
        for (int nt = 0; nt < 8; nt++) {
            const int col = cb0 + nt * 8;
            float2 bs2 = *(const float2*)&bias[col];
            const int r0 = rb0 + mt * 16;
            const int r1 = r0 + 8;
            float v00 = acc[mt][nt][0] + bs2.x;
            float v01 = acc[mt][nt][1] + bs2.y;
            float v10 = acc[mt][nt][2] + bs2.x;
            float v11 = acc[mt][nt][3] + bs2.y;
            if (EPI == 2) {
                v00 = gelu_f(v00); v01 = gelu_f(v01);
                v10 = gelu_f(v10); v11 = gelu_f(v11);
                __nv_bfloat16* Y = (__nv_bfloat16*)Cout;
                unsigned hh0 = pack_hi2(v00, v01), ll0 = pack_lo2(v00, v01);
                unsigned hh1 = pack_hi2(v10, v11), ll1 = pack_lo2(v10, v11);
                const size_t b0 = (size_t)r0 * 3 * N + col;
                const size_t b1 = (size_t)r1 * 3 * N + col;
                *(unsigned*)&Y[b0]         = hh0;
                *(unsigned*)&Y[b0 + N]     = ll0;
                *(unsigned*)&Y[b0 + 2*N]   = hh0;
                *(unsigned*)&Y[b1]         = hh1;
                *(unsigned*)&Y[b1 + N]     = ll1;
                *(unsigned*)&Y[b1 + 2*N]   = hh1;
            } else {
                float* C = (float*)Cout;
                if (EPI == 1) {
                    float2 x0 = *(const float2*)&R[(size_t)r0 * N + col];
                    float2 x1 = *(const float2*)&R[(size_t)r1 * N + col];
                    v00 += x0.x; v01 += x0.y; v10 += x1.x; v11 += x1.y;
                }
                float2 o0; o0.x = v00; o0.y = v01;
                float2 o1; o1.x = v10; o1.y = v11;
                *(float2*)&C[(size_t)r0 * N + col] = o0;
                *(float2*)&C[(size_t)r1 * N + col] = o1;
            }
        }
    }
}

// ---------------- Flash attention, bf16 tensor cores (split 3-term) ----------
// grid (32, 16, 2), block 128 (4 warps, warp = 16 q-rows).
// smem: Qh/Ql [64][72], Kh/Kl [64][72], Vth/Vtl [64][72] (V transposed: [d][key])
#define AST 72
#define SM_QH 0
#define SM_QL (64*AST)
#define SM_KH (2*64*AST)
#define SM_KL (3*64*AST)
#define SM_VH (4*64*AST)
#define SM_VL (5*64*AST)
#define ATTN_SMEM (6*64*AST*2)

__global__ void __launch_bounds__(128) attn_kernel(const float* __restrict__ qkv,
                                                   float* __restrict__ o)
{
    extern __shared__ __nv_bfloat16 sm[];
    const int tid = threadIdx.x;
    const int lane = tid & 31, warp = tid >> 5;
    const int qt = blockIdx.x, head = blockIdx.y, bb = blockIdx.z;
    const size_t base = (size_t)bb * SEQ * (3 * DMODEL);
    const int hoff = head * DHD;

    const int lr = tid >> 1;             // 0..63
    const int lc = (tid & 1) * 32;       // 0 or 32

    // ---- load Q tile once -> Qh/Ql (scale folded: *0.125) ----
    {
        const float* src = qkv + base + (size_t)(qt * 64 + lr) * (3 * DMODEL) + hoff + lc;
        #pragma unroll
        for (int i = 0; i < 8; i++) {
            float4 v = *(const float4*)(src + 4 * i);
            v.x *= 0.125f; v.y *= 0.125f; v.z *= 0.125f; v.w *= 0.125f;
            const int c = lc + 4 * i;
            *(unsigned*)&sm[SM_QH + lr * AST + c]     = pack_hi2(v.x, v.y);
            *(unsigned*)&sm[SM_QH + lr * AST + c + 2] = pack_hi2(v.z, v.w);
            *(unsigned*)&sm[SM_QL + lr * AST + c]     = pack_lo2(v.x, v.y);
            *(unsigned*)&sm[SM_QL + lr * AST + c + 2] = pack_lo2(v.z, v.w);
        }
    }

    float m0 = -1e30f, m1 = -1e30f, l0 = 0.f, l1 = 0.f;
    float oacc[8][4];
    #pragma unroll
    for (int nt = 0; nt < 8; nt++)
        #pragma unroll
        for (int q = 0; q < 4; q++) oacc[nt][q] = 0.f;

    for (int kt = 0; kt <= qt; kt++) {
        // stage K/V tile through registers
        const float* ksrc = qkv + base + (size_t)(kt * 64 + lr) * (3 * DMODEL) + DMODEL + hoff + lc;
        const float* vsrc = ksrc + DMODEL;
        float4 kreg[8], vreg[8];
        #pragma unroll
        for (int i = 0; i < 8; i++) {
            kreg[i] = *(const float4*)(ksrc + 4 * i);
            vreg[i] = *(const float4*)(vsrc + 4 * i);
        }
        __syncthreads();   // prior tile's ldmatrix reads complete
        #pragma unroll
        for (int i = 0; i < 8; i++) {
            const int c = lc + 4 * i;
            *(unsigned*)&sm[SM_KH + lr * AST + c]     = pack_hi2(kreg[i].x, kreg[i].y);
            *(unsigned*)&sm[SM_KH + lr * AST + c + 2] = pack_hi2(kreg[i].z, kreg[i].w);
            *(unsigned*)&sm[SM_KL + lr * AST + c]     = pack_lo2(kreg[i].x, kreg[i].y);
            *(unsigned*)&sm[SM_KL + lr * AST + c + 2] = pack_lo2(kreg[i].z, kreg[i].w);
            float vv[4] = {vreg[i].x, vreg[i].y, vreg[i].z, vreg[i].w};
            #pragma unroll
            for (int j = 0; j < 4; j++) {
                __nv_bfloat16 hi = __float2bfloat16(vv[j]);
                __nv_bfloat16 lo = __float2bfloat16(vv[j] - __bfloat162float(hi));
                sm[SM_VH + (c + j) * AST + lr] = hi;
                sm[SM_VL + (c + j) * AST + lr] = lo;
            }
        }
        __syncthreads();

        // ---- S = Qh.Kh + Ql.Kh + Qh.Kl ----
        float s[8][4];
        #pragma unroll
        for (int nt = 0; nt < 8; nt++)
            #pragma unroll
            for (int q = 0; q < 4; q++) s[nt][q] = 0.f;

        #pragma unroll
        for (int pair = 0; pair < 3; pair++) {
            const int aoff = (pair == 1) ? SM_QL : SM_QH;
            const int boff = (pair == 2) ? SM_KL : SM_KH;
            #pragma unroll
            for (int ks = 0; ks < 4; ks++) {
                unsigned af[4];
                unsigned a = (unsigned)__cvta_generic_to_shared(
                    &sm[aoff + (warp * 16 + (lane & 15)) * AST + ks * 16 + (lane >> 4) * 8]);
                ldm4(af[0], af[1], af[2], af[3], a);
                #pragma unroll
                for (int np = 0; np < 4; np++) {
                    unsigned r0, r1, r2, r3;
                    unsigned ba = (unsigned)__cvta_generic_to_shared(
                        &sm[boff + (np * 16 + (lane & 15)) * AST + ks * 16 + (lane >> 4) * 8]);
                    ldm4(r0, r1, r2, r3, ba);
                    unsigned b0[2] = {r0, r2}, b1[2] = {r1, r3};
                    mma_bf16(s[np*2],   af, b0);
                    mma_bf16(s[np*2+1], af, b1);
                }
            }
        }

        // ---- causal mask (scale already folded into Q) ----
        if (kt == qt) {
            const int r0 = warp * 16 + (lane >> 2);
            #pragma unroll
            for (int nt = 0; nt < 8; nt++) {
                const int c0 = nt * 8 + (lane & 3) * 2;
                if (c0 > r0)         s[nt][0] = -1e30f;
                if (c0 + 1 > r0)     s[nt][1] = -1e30f;
                if (c0 > r0 + 8)     s[nt][2] = -1e30f;
                if (c0 + 1 > r0 + 8) s[nt][3] = -1e30f;
            }
        }

        // ---- online softmax ----
        float rm0 = -1e30f, rm1 = -1e30f;
        #pragma unroll
        for (int nt = 0; nt < 8; nt++) {
            rm0 = fmaxf(rm0, fmaxf(s[nt][0], s[nt][1]));
            rm1 = fmaxf(rm1, fmaxf(s[nt][2], s[nt][3]));
        }
        rm0 = fmaxf(rm0, __shfl_xor_sync(0xffffffffu, rm0, 1));
        rm0 = fmaxf(rm0, __shfl_xor_sync(0xffffffffu, rm0, 2));
        rm1 = fmaxf(rm1, __shfl_xor_sync(0xffffffffu, rm1, 1));
        rm1 = fmaxf(rm1, __shfl_xor_sync(0xffffffffu, rm1, 2));

        const float mn0 = fmaxf(m0, rm0), mn1 = fmaxf(m1, rm1);
        const float corr0 = __expf(m0 - mn0), corr1 = __expf(m1 - mn1);
        m0 = mn0; m1 = mn1;
        float ps0 = 0.f, ps1 = 0.f;
        #pragma unroll
        for (int nt = 0; nt < 8; nt++) {
            s[nt][0] = __expf(s[nt][0] - mn0); ps0 += s[nt][0];
            s[nt][1] = __expf(s[nt][1] - mn0); ps0 += s[nt][1];
            s[nt][2] = __expf(s[nt][2] - mn1); ps1 += s[nt][2];
            s[nt][3] = __expf(s[nt][3] - mn1); ps1 += s[nt][3];
        }
        ps0 += __shfl_xor_sync(0xffffffffu, ps0, 1);
        ps0 += __shfl_xor_sync(0xffffffffu, ps0, 2);
        ps1 += __shfl_xor_sync(0xffffffffu, ps1, 1);
        ps1 += __shfl_xor_sync(0xffffffffu, ps1, 2);
        l0 = l0 * corr0 + ps0;
        l1 = l1 * corr1 + ps1;
        #pragma unroll
        for (int nt = 0; nt < 8; nt++) {
            oacc[nt][0] *= corr0; oacc[nt][1] *= corr0;
            oacc[nt][2] *= corr1; oacc[nt][3] *= corr1;
        }

        // ---- pack P fragments (accumulator -> A-fragment mapping) ----
        unsigned ph[4][4], pl[4][4];
        #pragma unroll
        for (int ks = 0; ks < 4; ks++) {
            ph[ks][0] = pack_hi2(s[2*ks][0],   s[2*ks][1]);
            ph[ks][1] = pack_hi2(s[2*ks][2],   s[2*ks][3]);
            ph[ks][2] = pack_hi2(s[2*ks+1][0], s[2*ks+1][1]);
            ph[ks][3] = pack_hi2(s[2*ks+1][2], s[2*ks+1][3]);
            pl[ks][0] = pack_lo2(s[2*ks][0],   s[2*ks][1]);
            pl[ks][1] = pack_lo2(s[2*ks][2],   s[2*ks][3]);
            pl[ks][2] = pack_lo2(s[2*ks+1][0], s[2*ks+1][1]);
            pl[ks][3] = pack_lo2(s[2*ks+1][2], s[2*ks+1][3]);
        }

        // ---- O += Ph.Vh + Pl.Vh + Ph.Vl ----
        #pragma unroll
        for (int pair = 0; pair < 3; pair++) {
            const int boff = (pair == 2) ? SM_VL : SM_VH;
            #pragma unroll
            for (int ks = 0; ks < 4; ks++) {
                const unsigned* af = (pair == 1) ? pl[ks] : ph[ks];
                #pragma unroll
                for (int np = 0; np < 4; np++) {
                    unsigned r0, r1, r2, r3;
                    unsigned ba = (unsigned)__cvta_generic_to_shared(
                        &sm[boff + (np * 16 + (lane & 15)) * AST + ks * 16 + (lane >> 4) * 8]);
                    ldm4(r0, r1, r2, r3, ba);
                    unsigned b0[2] = {r0, r2}, b1[2] = {r1, r3};
                    mma_bf16(oacc[np*2],   af, b0);
                    mma_bf16(oacc[np*2+1], af, b1);
                }
            }
        }
    }

    // ---- epilogue ----
    const float inv0 = 1.0f / l0, inv1 = 1.0f / l1;
    const int row0 = qt * 64 + warp * 16 + (lane >> 2);
    #pragma unroll
    for (int nt = 0; nt < 8; nt++) {
        const int col = hoff + nt * 8 + (lane & 3) * 2;
        float* d0 = o + (size_t)(bb * SEQ + row0) * DMODEL + col;
        float* d1 = d0 + 8 * DMODEL;
        float2 w0; w0.x = oacc[nt][0] * inv0; w0.y = oacc[nt][1] * inv0;
        float2 w1; w1.x = oacc[nt][2] * inv1; w1.y = oacc[nt][3] * inv1;
        *(float2*)d0 = w0;
        *(float2*)d1 = w1;
    }
}

// ---------------- launch ----------------------------------------------------
extern "C" void kernel_launch(void* const* d_in, const int* in_sizes, int n_in,
                              void* d_out, int out_size)
{
    const float* x      = (const float*)d_in[0];
    const float* ln1_g  = (const float*)d_in[1];
    const float* ln1_b  = (const float*)d_in[2];
    const float* W_attn = (const float*)d_in[3];
    const float* b_attn = (const float*)d_in[4];
    const float* W_proj = (const float*)d_in[5];
    const float* b_proj = (const float*)d_in[6];
    const float* ln2_g  = (const float*)d_in[7];
    const float* ln2_b  = (const float*)d_in[8];
    const float* W_up   = (const float*)d_in[9];
    const float* b_up   = (const float*)d_in[10];
    const float* W_down = (const float*)d_in[11];
    const float* b_down = (const float*)d_in[12];
    float* out = (float*)d_out;

    float *qkv, *o;
    __nv_bfloat16 *Aa, *Aup, *Bw;
    cudaGetSymbolAddress((void**)&qkv, g_qkv);
    cudaGetSymbolAddress((void**)&o,   g_o);
    cudaGetSymbolAddress((void**)&Aa,  g_Aa);
    cudaGetSymbolAddress((void**)&Aup, g_Aup);
    cudaGetSymbolAddress((void**)&Bw,  g_Bw);

    cudaFuncSetAttribute(attn_kernel, cudaFuncAttributeMaxDynamicSharedMemorySize, ATTN_SMEM);

    // 1. LN1 -> Aa (bf16 split triple)
    ln_bf16_kernel<<<NTOK, 256>>>(x, ln1_g, ln1_b, Aa);
    // 2. W_attn -> Bw
    convW_kernel<<<(3 * DMODEL * DMODEL + 255) / 256, 256>>>(W_attn, Bw, 3 * DMODEL, DMODEL);
    // 3. qkv = h @ W_attn^T + b_attn
    gemm_bf16<0><<<dim3(3 * DMODEL / 128, NTOK / 128), 256>>>(Aa, Bw, b_attn, nullptr, qkv,
                                                              NTOK, 3 * DMODEL, 3 * DMODEL);
    // 4. attention -> o (fp32), tensor cores
    attn_kernel<<<dim3(SEQ / 64, NH, BATCH), 128, ATTN_SMEM>>>(qkv, o);
    // 5. o -> Aa
    convA_kernel<<<(NTOK * DMODEL + 255) / 256, 256>>>(o, Aa, NTOK, DMODEL);
    // 6. W_proj -> Bw
    convW_kernel<<<(DMODEL * DMODEL + 255) / 256, 256>>>(W_proj, Bw, DMODEL, DMODEL);
    // 7. out = x + o @ W_proj^T + b_proj
    gemm_bf16<1><<<dim3(DMODEL / 128, NTOK / 128), 256>>>(Aa, Bw, b_proj, x, out,
                                                          NTOK, DMODEL, 3 * DMODEL);
    // 8. LN2 -> Aa
    ln_bf16_kernel<<<NTOK, 256>>>(out, ln2_g, ln2_b, Aa);
    // 9. W_up -> Bw
    convW_kernel<<<(4 * DMODEL * DMODEL + 255) / 256, 256>>>(W_up, Bw, 4 * DMODEL, DMODEL);
    // 10. Aup = split(gelu(h2 @ W_up^T + b_up))
    gemm_bf16<2><<<dim3(4 * DMODEL / 128, NTOK / 128), 256>>>(Aa, Bw, b_up, nullptr, Aup,
                                                              NTOK, 4 * DMODEL, 3 * DMODEL);
    // 11. W_down -> Bw
    convW_kernel<<<(DMODEL * 4 * DMODEL + 255) / 256, 256>>>(W_down, Bw, DMODEL, 4 * DMODEL);
    // 12. out = out + up @ W_down^T + b_down
    gemm_bf16<1><<<dim3(DMODEL / 128, NTOK / 128), 256>>>(Aup, Bw, b_down, out, out,
                                                          NTOK, DMODEL, 3 * 4 * DMODEL);
}